// round 13
// baseline (speedup 1.0000x reference)
#include <cuda_runtime.h>
#include <cstdint>

// Problem constants
#define B_   256
#define T_   512
#define IDIM 64
#define H_   256
#define G4   1024              // 4*H
#define BT   (B_ * T_)

// ---------------- scratch (device globals; no allocs allowed) ----------------
__device__ float g_xg[BT * G4];        // 536 MB: gate pre-activations (reused for both layers)
__device__ float g_h1[BT * H_];        // 134 MB: layer-0 hidden states (input to layer-1 projection)
__device__ float g_hbuf[2 * H_ * B_];  // ping-pong h, layout [buf][k][b]
__device__ float g_last[B_ * H_];      // final h2
__device__ float g_weff[4 * H_];       // collapsed head weight (W2@W1)
__device__ float g_beff[4];            // collapsed head bias

// ---------------- activations ----------------
__device__ __forceinline__ float sigm_(float x) {
    return 1.0f / (1.0f + __expf(-x));
}
__device__ __forceinline__ float tanh_(float x) {
    // 2*sigmoid(2x)-1 ; saturates correctly at +-inf
    return 2.0f / (1.0f + __expf(-2.0f * x)) - 1.0f;
}

// ---------------- GEMM: C[M][1024] = A[M][K] @ W[1024][K]^T + (bA+bB) ----------------
// Tiles 128x128x16, 256 threads, 8x8 microtile. M = 131072, grid = (8, 1024).
__global__ void __launch_bounds__(256) gemm_bias_kernel(
    const float* __restrict__ A, const float* __restrict__ W,
    const float* __restrict__ bA, const float* __restrict__ bB,
    float* __restrict__ C, int K)
{
    __shared__ float As[16][132];
    __shared__ float Ws[16][132];
    const int tid = threadIdx.x;
    const int tx = tid & 15;
    const int ty = tid >> 4;
    const int m0 = blockIdx.y * 128;
    const int n0 = blockIdx.x * 128;

    float acc[8][8];
#pragma unroll
    for (int i = 0; i < 8; i++)
#pragma unroll
        for (int j = 0; j < 8; j++) acc[i][j] = 0.f;

    const int lr = tid >> 2;            // 0..63
    const int lk = (tid & 3) << 2;      // 0,4,8,12
    const float* Ab = A + (size_t)m0 * K;
    const float* Wb = W + (size_t)n0 * K;

    for (int k0 = 0; k0 < K; k0 += 16) {
#pragma unroll
        for (int h = 0; h < 2; h++) {
            int r = lr + 64 * h;
            float4 av = *(const float4*)(Ab + (size_t)r * K + k0 + lk);
            As[lk + 0][r] = av.x; As[lk + 1][r] = av.y;
            As[lk + 2][r] = av.z; As[lk + 3][r] = av.w;
            float4 wv = *(const float4*)(Wb + (size_t)r * K + k0 + lk);
            Ws[lk + 0][r] = wv.x; Ws[lk + 1][r] = wv.y;
            Ws[lk + 2][r] = wv.z; Ws[lk + 3][r] = wv.w;
        }
        __syncthreads();
#pragma unroll
        for (int k = 0; k < 16; k++) {
            float a[8], w[8];
            *(float4*)(a)     = *(const float4*)(&As[k][ty * 8]);
            *(float4*)(a + 4) = *(const float4*)(&As[k][ty * 8 + 4]);
            *(float4*)(w)     = *(const float4*)(&Ws[k][tx * 8]);
            *(float4*)(w + 4) = *(const float4*)(&Ws[k][tx * 8 + 4]);
#pragma unroll
            for (int i = 0; i < 8; i++)
#pragma unroll
                for (int j = 0; j < 8; j++)
                    acc[i][j] = fmaf(a[i], w[j], acc[i][j]);
        }
        __syncthreads();
    }

    float bias[8];
#pragma unroll
    for (int j = 0; j < 8; j++) {
        int col = n0 + tx * 8 + j;
        bias[j] = bA[col] + bB[col];
    }
#pragma unroll
    for (int i = 0; i < 8; i++) {
        int row = m0 + ty * 8 + i;
        float* cp = C + (size_t)row * G4 + n0 + tx * 8;
        float4 o0 = make_float4(acc[i][0] + bias[0], acc[i][1] + bias[1],
                                acc[i][2] + bias[2], acc[i][3] + bias[3]);
        float4 o1 = make_float4(acc[i][4] + bias[4], acc[i][5] + bias[5],
                                acc[i][6] + bias[6], acc[i][7] + bias[7]);
        *(float4*)cp = o0;
        *(float4*)(cp + 4) = o1;
    }
}

// ---------------- LSTM scan ----------------
// Grid (8, 16), cluster (8,1,1). blockIdx.y = batch group (16 rows),
// blockIdx.x = slice s: CTA owns hidden units [s*32, s*32+32) i.e. 128 gate rows.
// Weights slice (128 x 256 fp32 = 128KB) resident in SMEM for all 512 steps.
// h exchanged via global ping-pong g_hbuf[buf][k][b] with __ldcg (L1 bypass);
// one barrier.cluster per step gives release/acquire ordering.
#define SCAN_SMEM ((256 * 128 + 256 * 16 + 128 * 17) * 4)

__global__ void __launch_bounds__(256, 1) __cluster_dims__(8, 1, 1)
lstm_scan_kernel(const float* __restrict__ xg, const float* __restrict__ Whh,
                 float* __restrict__ h_arch, float* __restrict__ h_last)
{
    extern __shared__ float sm[];
    float* w_s = sm;                          // [k=256][c=128]
    float* h_s = sm + 256 * 128;              // [k=256][b=16]
    float* g_s = sm + 256 * 128 + 256 * 16;   // [r=128][b=16] stride 17

    const int s   = blockIdx.x;           // 0..7
    const int gb0 = blockIdx.y * 16;      // batch base
    const int tid = threadIdx.x;
    const int tx  = tid & 15;             // local batch
    const int ty  = tid >> 4;             // row-block

    // Load weight slice into SMEM once. Column c in [0,128): gate = c>>5, unit = c&31.
    for (int idx = tid; idx < 128 * 64; idx += 256) {
        int c  = idx >> 6;
        int kq = (idx & 63) << 2;
        int gr = ((c >> 5) << 8) + s * 32 + (c & 31);   // global gate row
        float4 v = *(const float4*)(Whh + (size_t)gr * 256 + kq);
        w_s[(kq + 0) * 128 + c] = v.x;
        w_s[(kq + 1) * 128 + c] = v.y;
        w_s[(kq + 2) * 128 + c] = v.z;
        w_s[(kq + 3) * 128 + c] = v.w;
    }
    // Zero h(0) in our slice of ping buffer 0.
    for (int idx = tid; idx < 512; idx += 256) {
        int ul = idx >> 4, b = idx & 15;
        g_hbuf[(s * 32 + ul) * 256 + gb0 + b] = 0.f;
    }

    // c-state lives in registers: thread owns flat pairs f = tid*2, tid*2+1 over (b*32+ul)
    float cc0 = 0.f, cc1 = 0.f;
    const int f0 = tid * 2;
    const int b0 = f0 >> 5, u0 = f0 & 31;
    const int b1 = b0,      u1 = u0 + 1;
    const int rowbase = ((ty >> 2) << 8) + s * 32 + ((ty & 3) << 3);

    __threadfence();
    asm volatile("barrier.cluster.arrive.aligned;\n" ::: "memory");
    asm volatile("barrier.cluster.wait.aligned;\n" ::: "memory");

    for (int t = 0; t < T_; t++) {
        const int cur = t & 1;

        // Prefetch this thread's xg slice early (DRAM latency hidden behind h-tile load)
        const float* xp = xg + ((size_t)(gb0 + tx) * T_ + t) * (size_t)G4 + rowbase;
        float4 v0 = *(const float4*)xp;
        float4 v1 = *(const float4*)(xp + 4);

        // Phase A: load h(t-1) tile [256 x 16] from L2 (coherent path)
        const float* hb = g_hbuf + cur * (H_ * B_);
#pragma unroll
        for (int i = 0; i < 16; i++) {
            int k = i * 16 + ty;
            h_s[k * 16 + tx] = __ldcg(hb + k * 256 + gb0 + tx);
        }
        __syncthreads();

        // Phase B: gates = xg_t + h @ Whh_slice^T ; thread = 8 gate rows x 1 batch
        float acc[8];
        acc[0] = v0.x; acc[1] = v0.y; acc[2] = v0.z; acc[3] = v0.w;
        acc[4] = v1.x; acc[5] = v1.y; acc[6] = v1.z; acc[7] = v1.w;
#pragma unroll 8
        for (int k = 0; k < 256; k++) {
            float hv = h_s[k * 16 + tx];
            float4 wa = *(const float4*)(&w_s[k * 128 + ty * 8]);
            float4 wb = *(const float4*)(&w_s[k * 128 + ty * 8 + 4]);
            acc[0] = fmaf(hv, wa.x, acc[0]);
            acc[1] = fmaf(hv, wa.y, acc[1]);
            acc[2] = fmaf(hv, wa.z, acc[2]);
            acc[3] = fmaf(hv, wa.w, acc[3]);
            acc[4] = fmaf(hv, wb.x, acc[4]);
            acc[5] = fmaf(hv, wb.y, acc[5]);
            acc[6] = fmaf(hv, wb.z, acc[6]);
            acc[7] = fmaf(hv, wb.w, acc[7]);
        }
#pragma unroll
        for (int i = 0; i < 8; i++)
            g_s[(ty * 8 + i) * 17 + tx] = acc[i];
        __syncthreads();

        // Phase C: gate math, c/h update, publish h(t)
        float* hn = g_hbuf + (cur ^ 1) * (H_ * B_);
        {
            float iv = sigm_(g_s[(u0     ) * 17 + b0]);
            float fv = sigm_(g_s[(u0 + 32) * 17 + b0]);
            float gv = tanh_(g_s[(u0 + 64) * 17 + b0]);
            float ov = sigm_(g_s[(u0 + 96) * 17 + b0]);
            cc0 = fv * cc0 + iv * gv;
            float hh = ov * tanh_(cc0);
            hn[(s * 32 + u0) * 256 + gb0 + b0] = hh;
            if (h_arch) h_arch[((size_t)(gb0 + b0) * T_ + t) * H_ + s * 32 + u0] = hh;
            if (h_last && t == T_ - 1) h_last[(gb0 + b0) * H_ + s * 32 + u0] = hh;
        }
        {
            float iv = sigm_(g_s[(u1     ) * 17 + b1]);
            float fv = sigm_(g_s[(u1 + 32) * 17 + b1]);
            float gv = tanh_(g_s[(u1 + 64) * 17 + b1]);
            float ov = sigm_(g_s[(u1 + 96) * 17 + b1]);
            cc1 = fv * cc1 + iv * gv;
            float hh = ov * tanh_(cc1);
            hn[(s * 32 + u1) * 256 + gb0 + b1] = hh;
            if (h_arch) h_arch[((size_t)(gb0 + b1) * T_ + t) * H_ + s * 32 + u1] = hh;
            if (h_last && t == T_ - 1) h_last[(gb0 + b1) * H_ + s * 32 + u1] = hh;
        }

        // Release writes + wait for all 8 CTAs of the cluster (acquire)
        asm volatile("barrier.cluster.arrive.aligned;\n" ::: "memory");
        asm volatile("barrier.cluster.wait.aligned;\n" ::: "memory");
    }
}

// ---------------- head: collapse W2@(W1 . + b1) + b2 into one linear map ----------------
__global__ void __launch_bounds__(256) head_pre_kernel(
    const float* __restrict__ W1, const float* __restrict__ b1,
    const float* __restrict__ W2, const float* __restrict__ b2)
{
    __shared__ float w2s[4 * 1280];
    const int tid = threadIdx.x;   // = hidden index h
    for (int idx = tid; idx < 4 * 1280; idx += 256) w2s[idx] = W2[idx];
    __syncthreads();

    float acc[4] = {0.f, 0.f, 0.f, 0.f};
    for (int j = 0; j < 1280; j++) {
        float w1v = W1[(size_t)j * 256 + tid];
#pragma unroll
        for (int o = 0; o < 4; o++) acc[o] = fmaf(w2s[o * 1280 + j], w1v, acc[o]);
    }
#pragma unroll
    for (int o = 0; o < 4; o++) g_weff[o * 256 + tid] = acc[o];

    if (tid < 4) {
        float bb = b2[tid];
        for (int j = 0; j < 1280; j++) bb = fmaf(w2s[tid * 1280 + j], b1[j], bb);
        g_beff[tid] = bb;
    }
}

__global__ void __launch_bounds__(256) head_final_kernel(float* __restrict__ out)
{
    int id = blockIdx.x * 256 + threadIdx.x;  // 0..1023
    int b = id >> 2, o = id & 3;
    float acc = g_beff[o];
    const float* lp = g_last + b * 256;
    const float* wp = g_weff + o * 256;
    for (int h = 0; h < 256; h++) acc = fmaf(lp[h], wp[h], acc);
    out[id] = acc;   // y[b][o], row-major [256,4]
}

// ---------------- launch ----------------
extern "C" void kernel_launch(void* const* d_in, const int* in_sizes, int n_in,
                              void* d_out, int out_size)
{
    const float* x    = (const float*)d_in[0];
    const float* Wih0 = (const float*)d_in[1];
    const float* Whh0 = (const float*)d_in[2];
    const float* bih0 = (const float*)d_in[3];
    const float* bhh0 = (const float*)d_in[4];
    const float* Wih1 = (const float*)d_in[5];
    const float* Whh1 = (const float*)d_in[6];
    const float* bih1 = (const float*)d_in[7];
    const float* bhh1 = (const float*)d_in[8];
    const float* W1   = (const float*)d_in[9];
    const float* b1   = (const float*)d_in[10];
    const float* W2   = (const float*)d_in[11];
    const float* b2   = (const float*)d_in[12];
    float* out = (float*)d_out;

    float *p_xg, *p_h1, *p_last;
    cudaGetSymbolAddress((void**)&p_xg, g_xg);
    cudaGetSymbolAddress((void**)&p_h1, g_h1);
    cudaGetSymbolAddress((void**)&p_last, g_last);

    cudaFuncSetAttribute(lstm_scan_kernel,
                         cudaFuncAttributeMaxDynamicSharedMemorySize, SCAN_SMEM);

    dim3 gemmGrid(8, 1024);  // N tiles x M tiles (M = 131072)
    dim3 scanGrid(8, 16);    // 8-CTA clusters x 16 batch groups

    // Layer 0: input projection, then scan (archives h1 for layer-1 projection)
    gemm_bias_kernel<<<gemmGrid, 256>>>(x, Wih0, bih0, bhh0, p_xg, IDIM);
    lstm_scan_kernel<<<scanGrid, 256, SCAN_SMEM>>>(p_xg, Whh0, p_h1, nullptr);

    // Layer 1: projection from h1, then scan (keeps only last h)
    gemm_bias_kernel<<<gemmGrid, 256>>>(p_h1, Wih1, bih1, bhh1, p_xg, H_);
    lstm_scan_kernel<<<scanGrid, 256, SCAN_SMEM>>>(p_xg, Whh1, nullptr, p_last);

    // Collapsed linear head
    head_pre_kernel<<<1, 256>>>(W1, b1, W2, b2);
    head_final_kernel<<<4, 256>>>(out);
}